// round 10
// baseline (speedup 1.0000x reference)
#include <cuda_runtime.h>
#include <math.h>

// energy[z] = sum_j feats[z,j] * Wtab[j] * charges[z, idx(j)]
// Wtab folds w_r = W_lin_r @ W_tp_r, region scales 1/sqrt3, 1/sqrt5,
// and alpha*lin_norm = 1/(16*sqrt(768)).
//
// Single fused kernel: first NBUILD blocks build gWtab (warp-per-entry),
// everyone spins on an arrive-counter (~1us, single wave: all blocks
// resident), then runs the proven R6 streaming loop verbatim. Counters are
// reset by the last departing block so every launch (incl. graph replays)
// starts clean.

#define MUL 256
#define FEAT 2304          // 9 * MUL
#define FEAT4 576          // float4 slots per node
#define N_NODES 65536
#define NPB 8              // nodes per group
#define NGROUPS (N_NODES / NPB)   // 8192
#define THREADS 288        // 9 warps; each thread owns 2 float4 slots
#define MAXBLK 5

__device__ float gWtab[FEAT];
__device__ unsigned int gArrive;   // builder blocks completed
__device__ unsigned int gDepart;   // blocks finished (last one resets)

// ---------------------------------------------------------------------------
__device__ __forceinline__ int class_of(int j) {
    if (j < MUL)          return 0;
    if (j < 4 * MUL)      return 1 + (j - MUL) % 3;
    return 4 + (j - 4 * MUL) % 5;
}

// ---------------------------------------------------------------------------
__global__ void __launch_bounds__(THREADS, MAXBLK)
readout_kernel(const float* __restrict__ feats,
               const float* __restrict__ charges,
               const float* __restrict__ Wl0,
               const float* __restrict__ Wl1,
               const float* __restrict__ Wl2,
               const float* __restrict__ Wt0,
               const float* __restrict__ Wt1,
               const float* __restrict__ Wt2,
               float* __restrict__ out) {
    __shared__ float cfac[NPB * 9];
    __shared__ float partials[NPB][THREADS / 32];

    const int t    = threadIdx.x;
    const int wid  = t >> 5;
    const int lane = t & 31;

    const unsigned int nbuild = (gridDim.x < 256u) ? gridDim.x : 256u;

    // ---- Phase 0: builder blocks fill gWtab (warp per entry) ----
    if (blockIdx.x < nbuild) {
        const float alpha_lin = 1.0f / (16.0f * sqrtf(768.0f));
        for (int j = (int)blockIdx.x * 9 + wid; j < FEAT;
             j += (int)nbuild * 9) {
            const float* Wl;
            const float* Wt;
            int u;
            float s;
            if (j < MUL) {
                u = j; Wl = Wl0; Wt = Wt0; s = 1.0f;
            } else if (j < 4 * MUL) {
                u = (j - MUL) / 3; Wl = Wl1; Wt = Wt1; s = rsqrtf(3.0f);
            } else {
                u = (j - 4 * MUL) / 5; Wl = Wl2; Wt = Wt2; s = rsqrtf(5.0f);
            }
            const float4* row = (const float4*)(Wl + (size_t)u * MUL);
            const float4* wt4 = (const float4*)Wt;
            float4 r0 = row[lane];
            float4 r1 = row[lane + 32];
            float4 q0 = wt4[lane];
            float4 q1 = wt4[lane + 32];
            float acc = r0.x * q0.x + r0.y * q0.y + r0.z * q0.z + r0.w * q0.w
                      + r1.x * q1.x + r1.y * q1.y + r1.z * q1.z + r1.w * q1.w;
            #pragma unroll
            for (int o = 16; o > 0; o >>= 1) {
                acc += __shfl_down_sync(0xffffffffu, acc, o);
            }
            if (lane == 0) gWtab[j] = acc * s * alpha_lin;
        }
        __syncthreads();            // all warps of this builder done
        if (t == 0) {
            __threadfence();        // release gWtab writes
            atomicAdd(&gArrive, 1u);
        }
    }

    // ---- Phase 1: everyone waits for all builders ----
    if (t == 0) {
        while (atomicAdd(&gArrive, 0u) < nbuild) {
            __nanosleep(200);
        }
    }
    __syncthreads();

    // ---- Hoist per-thread weights + class indices (node-invariant) ----
    float w0x, w0y, w0z, w0w, w1x, w1y, w1z, w1w;
    int i0x, i0y, i0z, i0w, i1x, i1y, i1z, i1w;
    {
        int j0 = t * 4;
        w0x = gWtab[j0 + 0]; i0x = class_of(j0 + 0);
        w0y = gWtab[j0 + 1]; i0y = class_of(j0 + 1);
        w0z = gWtab[j0 + 2]; i0z = class_of(j0 + 2);
        w0w = gWtab[j0 + 3]; i0w = class_of(j0 + 3);
        int j1 = (t + THREADS) * 4;
        w1x = gWtab[j1 + 0]; i1x = class_of(j1 + 0);
        w1y = gWtab[j1 + 1]; i1y = class_of(j1 + 1);
        w1z = gWtab[j1 + 2]; i1z = class_of(j1 + 2);
        w1w = gWtab[j1 + 3]; i1w = class_of(j1 + 3);
    }

    // ---- Phase 2: R6 streaming loop, verbatim ----
    for (int g = blockIdx.x; g < NGROUPS; g += gridDim.x) {
        const size_t z0 = (size_t)g * NPB;

        if (t < NPB * 9) {
            cfac[t] = charges[z0 * 9 + t];
        }
        __syncthreads();

        const float4* fbase = (const float4*)(feats + z0 * FEAT);

        // Prologue: loads for node 0.
        float4 a = fbase[t];
        float4 b = fbase[t + THREADS];

        #pragma unroll
        for (int n = 0; n < NPB; n++) {
            float4 a2, b2;
            if (n < NPB - 1) {
                const float4* fn = fbase + (size_t)(n + 1) * FEAT4;
                a2 = fn[t];
                b2 = fn[t + THREADS];
            }

            const float* cf = &cfac[n * 9];
            float acc;
            acc  = a.x * (w0x * cf[i0x]);
            acc += a.y * (w0y * cf[i0y]);
            acc += a.z * (w0z * cf[i0z]);
            acc += a.w * (w0w * cf[i0w]);
            acc += b.x * (w1x * cf[i1x]);
            acc += b.y * (w1y * cf[i1y]);
            acc += b.z * (w1z * cf[i1z]);
            acc += b.w * (w1w * cf[i1w]);

            #pragma unroll
            for (int o = 16; o > 0; o >>= 1) {
                acc += __shfl_down_sync(0xffffffffu, acc, o);
            }
            if (lane == 0) partials[n][wid] = acc;

            a = a2;
            b = b2;
        }
        __syncthreads();

        // Warp n (n < NPB) finalizes node n: reduce 9 warp-partials.
        if (wid < NPB) {
            float v = (lane < THREADS / 32) ? partials[wid][lane] : 0.0f;
            v += __shfl_down_sync(0xffffffffu, v, 8, 16);
            v += __shfl_down_sync(0xffffffffu, v, 4, 16);
            v += __shfl_down_sync(0xffffffffu, v, 2, 16);
            v += __shfl_down_sync(0xffffffffu, v, 1, 16);
            if (lane == 0) out[z0 + wid] = v;
        }
    }

    // ---- Epilogue: last block resets counters for the next launch ----
    __syncthreads();
    if (t == 0) {
        unsigned int old = atomicAdd(&gDepart, 1u);
        if (old == gridDim.x - 1u) {
            gArrive = 0u;
            gDepart = 0u;
            __threadfence();
        }
    }
}

// ---------------------------------------------------------------------------
extern "C" void kernel_launch(void* const* d_in, const int* in_sizes, int n_in,
                              void* d_out, int out_size) {
    const float* feats   = (const float*)d_in[0];
    const float* charges = (const float*)d_in[1];
    const float* Wl0     = (const float*)d_in[2];
    const float* Wl1     = (const float*)d_in[3];
    const float* Wl2     = (const float*)d_in[4];
    const float* Wt0     = (const float*)d_in[5];
    const float* Wt1     = (const float*)d_in[6];
    const float* Wt2     = (const float*)d_in[7];
    float* out = (float*)d_out;

    int dev = 0, sms = 152, nb = MAXBLK;
    cudaGetDevice(&dev);
    cudaDeviceGetAttribute(&sms, cudaDevAttrMultiProcessorCount, dev);
    cudaOccupancyMaxActiveBlocksPerMultiprocessor(&nb, readout_kernel,
                                                  THREADS, 0);
    if (nb < 1) nb = 1;
    if (nb > MAXBLK) nb = MAXBLK;
    int grid = sms * nb;              // single wave: all blocks resident
    if (grid > NGROUPS) grid = NGROUPS;

    readout_kernel<<<grid, THREADS>>>(feats, charges, Wl0, Wl1, Wl2,
                                      Wt0, Wt1, Wt2, out);
}

// round 11
// speedup vs baseline: 1.0899x; 1.0899x over previous
#include <cuda_runtime.h>
#include <math.h>

// energy[z] = sum_j feats[z,j] * Wtab[j] * charges[z, idx(j)]
// Wtab folds w_r = W_lin_r @ W_tp_r, region scales 1/sqrt3, 1/sqrt5,
// and alpha*lin_norm = 1/(16*sqrt(768)).
//
// Readout kernel is the R6 winner, byte-identical (98.9% of the measured
// LTS-cap floor ~6578 GB/s). Only build_tab is touched: float4 loads,
// 128-thread blocks.

#define MUL 256
#define FEAT 2304          // 9 * MUL
#define FEAT4 576          // float4 slots per node
#define N_NODES 65536
#define NPB 8              // nodes per group
#define NGROUPS (N_NODES / NPB)   // 8192
#define THREADS 288        // 9 warps; each thread owns 2 float4 slots
#define MAXBLK 5

__device__ float gWtab[FEAT];

// ---------------------------------------------------------------------------
// Prep: one warp per output j (2304 warps, 576 blocks of 128).
// Lane reads row as 2 coalesced LDG.128; shuffle-reduce; store.
// ---------------------------------------------------------------------------
__global__ void __launch_bounds__(128)
build_tab_kernel(const float* __restrict__ Wl0,
                 const float* __restrict__ Wl1,
                 const float* __restrict__ Wl2,
                 const float* __restrict__ Wt0,
                 const float* __restrict__ Wt1,
                 const float* __restrict__ Wt2) {
    int warp = (blockIdx.x * blockDim.x + threadIdx.x) >> 5;
    int lane = threadIdx.x & 31;
    if (warp >= FEAT) return;
    int j = warp;

    const float alpha_lin = 1.0f / (16.0f * sqrtf(768.0f));

    const float* Wl;
    const float* Wt;
    int u;
    float s;
    if (j < MUL) {
        u = j; Wl = Wl0; Wt = Wt0; s = 1.0f;
    } else if (j < 4 * MUL) {
        u = (j - MUL) / 3; Wl = Wl1; Wt = Wt1; s = rsqrtf(3.0f);
    } else {
        u = (j - 4 * MUL) / 5; Wl = Wl2; Wt = Wt2; s = rsqrtf(5.0f);
    }

    const float4* row4 = (const float4*)(Wl + (size_t)u * MUL);
    const float4* wt4  = (const float4*)Wt;
    float4 r0 = row4[lane];
    float4 r1 = row4[lane + 32];
    float4 q0 = wt4[lane];
    float4 q1 = wt4[lane + 32];
    float acc = r0.x * q0.x + r0.y * q0.y + r0.z * q0.z + r0.w * q0.w
              + r1.x * q1.x + r1.y * q1.y + r1.z * q1.z + r1.w * q1.w;
    #pragma unroll
    for (int o = 16; o > 0; o >>= 1) {
        acc += __shfl_down_sync(0xffffffffu, acc, o);
    }
    if (lane == 0) gWtab[j] = acc * s * alpha_lin;
}

// ---------------------------------------------------------------------------
__device__ __forceinline__ int class_of(int j) {
    if (j < MUL)          return 0;
    if (j < 4 * MUL)      return 1 + (j - MUL) % 3;
    return 4 + (j - 4 * MUL) % 5;
}

// ---------------------------------------------------------------------------
// Main readout: persistent static grid-stride over node groups of NPB=8.
// 288 threads; thread t owns float4 slots {t, t+288}. Node-invariant weights
// and class indices hoisted into registers. The 8-node loop is explicitly
// double-buffered: node n+1's two LDG.128 issue before node n's reduce chain,
// keeping >=4 LDG.128/thread in flight continuously.  (R6 verbatim.)
// ---------------------------------------------------------------------------
__global__ void __launch_bounds__(THREADS, MAXBLK)
readout_kernel(const float* __restrict__ feats,
               const float* __restrict__ charges,
               float* __restrict__ out) {
    __shared__ float cfac[NPB * 9];
    __shared__ float partials[NPB][THREADS / 32];

    const int t    = threadIdx.x;
    const int wid  = t >> 5;
    const int lane = t & 31;

    // Hoist per-thread weights + class indices (node-invariant).
    float w0x, w0y, w0z, w0w, w1x, w1y, w1z, w1w;
    int i0x, i0y, i0z, i0w, i1x, i1y, i1z, i1w;
    {
        int j0 = t * 4;
        w0x = gWtab[j0 + 0]; i0x = class_of(j0 + 0);
        w0y = gWtab[j0 + 1]; i0y = class_of(j0 + 1);
        w0z = gWtab[j0 + 2]; i0z = class_of(j0 + 2);
        w0w = gWtab[j0 + 3]; i0w = class_of(j0 + 3);
        int j1 = (t + THREADS) * 4;
        w1x = gWtab[j1 + 0]; i1x = class_of(j1 + 0);
        w1y = gWtab[j1 + 1]; i1y = class_of(j1 + 1);
        w1z = gWtab[j1 + 2]; i1z = class_of(j1 + 2);
        w1w = gWtab[j1 + 3]; i1w = class_of(j1 + 3);
    }

    for (int g = blockIdx.x; g < NGROUPS; g += gridDim.x) {
        const size_t z0 = (size_t)g * NPB;

        if (t < NPB * 9) {
            cfac[t] = charges[z0 * 9 + t];
        }
        __syncthreads();

        const float4* fbase = (const float4*)(feats + z0 * FEAT);

        // Prologue: loads for node 0.
        float4 a = fbase[t];
        float4 b = fbase[t + THREADS];

        #pragma unroll
        for (int n = 0; n < NPB; n++) {
            float4 a2, b2;
            if (n < NPB - 1) {
                const float4* fn = fbase + (size_t)(n + 1) * FEAT4;
                a2 = fn[t];
                b2 = fn[t + THREADS];
            }

            const float* cf = &cfac[n * 9];
            float acc;
            acc  = a.x * (w0x * cf[i0x]);
            acc += a.y * (w0y * cf[i0y]);
            acc += a.z * (w0z * cf[i0z]);
            acc += a.w * (w0w * cf[i0w]);
            acc += b.x * (w1x * cf[i1x]);
            acc += b.y * (w1y * cf[i1y]);
            acc += b.z * (w1z * cf[i1z]);
            acc += b.w * (w1w * cf[i1w]);

            #pragma unroll
            for (int o = 16; o > 0; o >>= 1) {
                acc += __shfl_down_sync(0xffffffffu, acc, o);
            }
            if (lane == 0) partials[n][wid] = acc;

            a = a2;
            b = b2;
        }
        __syncthreads();

        // Warp n (n < NPB) finalizes node n: reduce 9 warp-partials.
        if (wid < NPB) {
            float v = (lane < THREADS / 32) ? partials[wid][lane] : 0.0f;
            v += __shfl_down_sync(0xffffffffu, v, 8, 16);
            v += __shfl_down_sync(0xffffffffu, v, 4, 16);
            v += __shfl_down_sync(0xffffffffu, v, 2, 16);
            v += __shfl_down_sync(0xffffffffu, v, 1, 16);
            if (lane == 0) out[z0 + wid] = v;
        }
        // Next iteration's first __syncthreads orders cfac/partials rewrites
        // against this iteration's readers.
    }
}

// ---------------------------------------------------------------------------
extern "C" void kernel_launch(void* const* d_in, const int* in_sizes, int n_in,
                              void* d_out, int out_size) {
    const float* feats   = (const float*)d_in[0];
    const float* charges = (const float*)d_in[1];
    const float* Wl0     = (const float*)d_in[2];
    const float* Wl1     = (const float*)d_in[3];
    const float* Wl2     = (const float*)d_in[4];
    const float* Wt0     = (const float*)d_in[5];
    const float* Wt1     = (const float*)d_in[6];
    const float* Wt2     = (const float*)d_in[7];
    float* out = (float*)d_out;

    build_tab_kernel<<<(FEAT * 32 + 127) / 128, 128>>>(Wl0, Wl1, Wl2,
                                                       Wt0, Wt1, Wt2);

    int dev = 0, sms = 152, nb = MAXBLK;
    cudaGetDevice(&dev);
    cudaDeviceGetAttribute(&sms, cudaDevAttrMultiProcessorCount, dev);
    cudaOccupancyMaxActiveBlocksPerMultiprocessor(&nb, readout_kernel,
                                                  THREADS, 0);
    if (nb < 1) nb = 1;
    if (nb > MAXBLK) nb = MAXBLK;
    int grid = sms * nb;
    if (grid > NGROUPS) grid = NGROUPS;

    readout_kernel<<<grid, THREADS>>>(feats, charges, out);
}